// round 1
// baseline (speedup 1.0000x reference)
#include <cuda_runtime.h>

// AverageGridEncoder: scatter-mean of z over nearest grid cell, + latents.
// Counting-sort + gather design: avoids 51M float atomics (L2 atomic-ALU bound)
// in favor of streaming coalesced reads (DRAM bound, the true floor).

#define P0 128
#define P1 128
#define NCELLS (P0 * P1)      // 16384
#define EMBED 128
#define MAXB 4
#define MAXN 100000

// Scratch (allocation-free rule: __device__ globals)
__device__ int g_count[MAXB * NCELLS];
__device__ int g_offset[MAXB * NCELLS];
__device__ int g_cell[MAXB * MAXN];
__device__ int g_perm[MAXB * MAXN];

__global__ void zero_counts_kernel(int total) {
    int i = blockIdx.x * blockDim.x + threadIdx.x;
    if (i < total) g_count[i] = 0;
}

// Per-point cell index + histogram. step = (1-0)/(128-1) in f32, divide (not
// reciprocal-mul) and rintf (round-half-even) to match XLA's round((x-lo)/step).
__global__ void hist_kernel(const float* __restrict__ x, int BN, int N) {
    int i = blockIdx.x * blockDim.x + threadIdx.x;
    if (i >= BN) return;
    float2 p = reinterpret_cast<const float2*>(x)[i];
    const float step = 1.0f / 127.0f;
    int i0 = (int)rintf(p.x / step);
    int i1 = (int)rintf(p.y / step);
    i0 = min(max(i0, 0), P0 - 1);
    i1 = min(max(i1, 0), P1 - 1);
    int cell = i0 * P1 + i1;
    g_cell[i] = cell;
    int b = i / N;
    atomicAdd(&g_count[b * NCELLS + cell], 1);
}

// One block per batch: exclusive prefix sum over 16384 counts.
// 1024 threads x 16 cells each, Hillis-Steele block scan over thread totals.
__global__ void scan_kernel() {
    __shared__ int s[1024];
    int b = blockIdx.x;
    int t = threadIdx.x;
    int base = b * NCELLS;
    int local[16];
    int sum = 0;
#pragma unroll
    for (int k = 0; k < 16; k++) {
        local[k] = g_count[base + t * 16 + k];
        sum += local[k];
    }
    s[t] = sum;
    __syncthreads();
    for (int off = 1; off < 1024; off <<= 1) {
        int v = (t >= off) ? s[t - off] : 0;
        __syncthreads();
        s[t] += v;
        __syncthreads();
    }
    int run = s[t] - sum;  // exclusive prefix for this thread's chunk
#pragma unroll
    for (int k = 0; k < 16; k++) {
        g_offset[base + t * 16 + k] = run;
        run += local[k];
    }
}

// Assign each point a slot inside its cell's contiguous range.
// After this kernel, g_offset[c] == end position of cell c (start + count).
__global__ void scatter_kernel(int BN, int N) {
    int i = blockIdx.x * blockDim.x + threadIdx.x;
    if (i >= BN) return;
    int b = i / N;
    int n = i - b * N;
    int cell = g_cell[i];
    int slot = atomicAdd(&g_offset[b * NCELLS + cell], 1);
    g_perm[b * N + slot] = n;
}

// One warp per (batch, cell). Each lane owns 4 embed dims (float4).
// Per point in the cell: one fully-coalesced 512B LDG.128 burst per warp.
__global__ void gather_kernel(const float* __restrict__ z,
                              const float* __restrict__ latents,
                              float* __restrict__ out_x,
                              float* __restrict__ out_z,
                              int B, int N) {
    int gwarp = (blockIdx.x * blockDim.x + threadIdx.x) >> 5;
    int lane = threadIdx.x & 31;
    int total = B * NCELLS;
    if (gwarp >= total) return;

    int b = gwarp / NCELLS;
    int cell = gwarp - b * NCELLS;
    int idx = gwarp;  // b*NCELLS + cell

    int end = g_offset[idx];   // post-scatter: start + count
    int cnt = g_count[idx];
    int start = end - cnt;

    const float4* zb = reinterpret_cast<const float4*>(z) +
                       (size_t)b * N * (EMBED / 4);
    const int* perm = g_perm + b * N;

    float4 acc0 = make_float4(0.f, 0.f, 0.f, 0.f);
    float4 acc1 = make_float4(0.f, 0.f, 0.f, 0.f);
    int k = start;
    for (; k + 1 < end; k += 2) {
        int p0 = perm[k];
        int p1 = perm[k + 1];
        float4 v0 = zb[(size_t)p0 * (EMBED / 4) + lane];
        float4 v1 = zb[(size_t)p1 * (EMBED / 4) + lane];
        acc0.x += v0.x; acc0.y += v0.y; acc0.z += v0.z; acc0.w += v0.w;
        acc1.x += v1.x; acc1.y += v1.y; acc1.z += v1.z; acc1.w += v1.w;
    }
    if (k < end) {
        int p0 = perm[k];
        float4 v0 = zb[(size_t)p0 * (EMBED / 4) + lane];
        acc0.x += v0.x; acc0.y += v0.y; acc0.z += v0.z; acc0.w += v0.w;
    }
    acc0.x += acc1.x; acc0.y += acc1.y; acc0.z += acc1.z; acc0.w += acc1.w;

    float inv = (cnt > 0) ? (1.0f / (float)cnt) : 0.0f;
    float4 l = reinterpret_cast<const float4*>(latents)[cell * (EMBED / 4) + lane];
    float4 o;
    o.x = l.x + acc0.x * inv;
    o.y = l.y + acc0.y * inv;
    o.z = l.z + acc0.z * inv;
    o.w = l.w + acc0.w * inv;
    reinterpret_cast<float4*>(out_z)[(size_t)idx * (EMBED / 4) + lane] = o;

    if (lane == 0) {
        int i0 = cell / P1;
        int i1 = cell - i0 * P1;
        const float step = 1.0f / 127.0f;
        float2 g = make_float2((float)i0 * step, (float)i1 * step);
        reinterpret_cast<float2*>(out_x)[idx] = g;
    }
}

extern "C" void kernel_launch(void* const* d_in, const int* in_sizes, int n_in,
                              void* d_out, int out_size) {
    // Identify inputs by size: z is largest, x is smallest, latents in between.
    int ix = 0, iz = 0, il = 0;
    for (int i = 1; i < n_in; i++) {
        if (in_sizes[i] > in_sizes[iz]) iz = i;
        if (in_sizes[i] < in_sizes[ix]) ix = i;
    }
    for (int i = 0; i < n_in; i++)
        if (i != ix && i != iz) il = i;

    const float* x = (const float*)d_in[ix];
    const float* z = (const float*)d_in[iz];
    const float* latents = (const float*)d_in[il];

    int BN = in_sizes[ix] / 2;                        // B*N
    int B = out_size / (NCELLS * (2 + EMBED));        // per-batch out = 16384*130
    if (B < 1) B = 1;
    int N = BN / B;

    float* out_x = (float*)d_out;                     // [B,128,128,2]
    float* out_z = (float*)d_out + (size_t)B * NCELLS * 2;  // [B,128,128,128]

    int cells = B * NCELLS;
    zero_counts_kernel<<<(cells + 255) / 256, 256>>>(cells);
    hist_kernel<<<(BN + 255) / 256, 256>>>(x, BN, N);
    scan_kernel<<<B, 1024>>>();
    scatter_kernel<<<(BN + 255) / 256, 256>>>(BN, N);
    int threads_total = cells * 32;                   // one warp per cell
    gather_kernel<<<(threads_total + 255) / 256, 256>>>(z, latents, out_x, out_z, B, N);
}